// round 16
// baseline (speedup 1.0000x reference)
#include <cuda_runtime.h>

#define NN    2048
#define DIN   128
#define HH    256
#define DEMB  64
#define NSTRIP 8
#define STRIPJ (NN / NSTRIP)   // 256
#define BI    64
#define BJ    64
#define RA    8                // rows per kA block
#define XPAD  10               // oxT row pad

// -------- device scratch (no allocations allowed) --------
__device__ __align__(16) float g_emb[NN * DEMB];            // 512 KB
__device__ __align__(16) float g_sq[NN];                    // 8 KB
__device__ __align__(16) float g_xlast[NN * DIN];           // 1 MB
__device__ __align__(16) float g_ypart[NSTRIP * NN * DIN];  // 8 MB
__device__ __align__(16) float g_degpart[NSTRIP * NN];      // 64 KB

// -------- packed fp32x2 helpers (exact fp32, 2 FMA / instr) --------
typedef unsigned long long ull;
__device__ __forceinline__ ull pk2(float a, float b) {
    ull r; asm("mov.b64 %0, {%1, %2};" : "=l"(r) : "f"(a), "f"(b)); return r;
}
__device__ __forceinline__ void fma2(ull& d, ull a, ull b) {
    asm("fma.rn.f32x2 %0, %1, %2, %0;" : "+l"(d) : "l"(a), "l"(b));
}
__device__ __forceinline__ float2 upk(ull v) {
    float2 f; asm("mov.b64 {%0, %1}, %2;" : "=f"(f.x), "=f"(f.y) : "l"(v)); return f;
}
// sigmoid via single-MUFU tanh: sigmoid(z) = 0.5*tanh(z/2) + 0.5
__device__ __forceinline__ float sigmoidf(float z) {
    float th;
    const float h = 0.5f * z;
    asm("tanh.approx.f32 %0, %1;" : "=f"(th) : "f"(h));
    return fmaf(0.5f, th, 0.5f);
}

// ============================================================
// Kernel A: out_x = relu(x@W0+b0); emb = relu(out_x@W1+b1);
//           sq = rowsum(emb^2); x_last = x@W2+b2
// 256 blocks x 8 rows, 512 threads. Zero-MOV inner loops:
// weight col-pairs loaded natively as ull; x pre-duplicated
// (v,v) in smem. Warps 0-7: stage1; warps 8-15: stage3.
// ============================================================
__global__ void __launch_bounds__(512) kA(
    const float* __restrict__ x,
    const float* __restrict__ W0, const float* __restrict__ b0,
    const float* __restrict__ W1, const float* __restrict__ b1,
    const float* __restrict__ W2, const float* __restrict__ b2)
{
    __shared__ ull   xsTd[DIN][RA];    // x transposed, dup pairs (8 KB)
    __shared__ float oxT[HH][XPAD];    // out_x transposed
    __shared__ float embS[RA][DEMB + 1];
    __shared__ float red[3 * 128 * 4]; // stage2 k-split partials

    const int t = threadIdx.x;
    const int row0 = blockIdx.x * RA;

    // load x rows transposed, duplicated
    #pragma unroll
    for (int idx = t; idx < RA * DIN; idx += 512) {
        const int r = idx >> 7, k = idx & 127;
        const float v = x[row0 * DIN + idx];
        xsTd[k][r] = pk2(v, v);
    }
    __syncthreads();

    // ---- stage 1 (warps 0-7) + stage 3 (warps 8-15) ----
    if (t < 256) {
        // stage 1: cols {2cp, 2cp+1} x rows {4rg..4rg+3}
        const int cp = t & 127;
        const int rg = t >> 7;
        const float* w0p = W0 + 2 * cp;
        ull acc[4] = {0ULL, 0ULL, 0ULL, 0ULL};

        #pragma unroll 2
        for (int kk = 0; kk < DIN; kk += 8) {
            ull wb[8];
            #pragma unroll
            for (int u = 0; u < 8; u++)
                wb[u] = *(const ull*)(w0p + (kk + u) * HH);
            #pragma unroll
            for (int u = 0; u < 8; u++) {
                const ulonglong2 x01 = *(const ulonglong2*)&xsTd[kk + u][4 * rg];
                const ulonglong2 x23 = *(const ulonglong2*)&xsTd[kk + u][4 * rg + 2];
                fma2(acc[0], wb[u], x01.x);
                fma2(acc[1], wb[u], x01.y);
                fma2(acc[2], wb[u], x23.x);
                fma2(acc[3], wb[u], x23.y);
            }
        }
        const float bb0 = b0[2 * cp];
        const float bb1 = b0[2 * cp + 1];
        #pragma unroll
        for (int rr = 0; rr < 4; rr++) {
            const float2 v = upk(acc[rr]);
            oxT[2 * cp][4 * rg + rr]     = fmaxf(v.x + bb0, 0.f);
            oxT[2 * cp + 1][4 * rg + rr] = fmaxf(v.y + bb0 + (bb1 - bb0), 0.f);
        }
        // note: second col uses bb1; expression kept simple:
        // (v.y + bb0 + (bb1-bb0)) == v.y + bb1 exactly only if bb0 terms cancel;
        // to stay exact, rewrite below.
        #pragma unroll
        for (int rr = 0; rr < 4; rr++) {
            const float2 v = upk(acc[rr]);
            oxT[2 * cp + 1][4 * rg + rr] = fmaxf(v.y + bb1, 0.f);
        }
    } else {
        // stage 3: cols {2cp, 2cp+1} x rows {2rg, 2rg+1}
        const int s  = t - 256;
        const int cp = s & 63;
        const int rg = s >> 6;            // 0..3
        const float* w2p = W2 + 2 * cp;
        ull acc[2] = {0ULL, 0ULL};

        #pragma unroll 2
        for (int kk = 0; kk < DIN; kk += 8) {
            ull wb[8];
            #pragma unroll
            for (int u = 0; u < 8; u++)
                wb[u] = *(const ull*)(w2p + (kk + u) * DIN);
            #pragma unroll
            for (int u = 0; u < 8; u++) {
                const ulonglong2 x01 = *(const ulonglong2*)&xsTd[kk + u][2 * rg];
                fma2(acc[0], wb[u], x01.x);
                fma2(acc[1], wb[u], x01.y);
            }
        }
        const float bb0 = b2[2 * cp];
        const float bb1 = b2[2 * cp + 1];
        #pragma unroll
        for (int rr = 0; rr < 2; rr++) {
            const float2 v = upk(acc[rr]);
            *(float2*)(g_xlast + (size_t)(row0 + 2 * rg + rr) * DIN + 2 * cp) =
                make_float2(v.x + bb0, v.y + bb1);
        }
    }
    __syncthreads();

    // ---- stage 2: emb [8, 64]; e = t&63, k-quarter split ----
    {
        const int e  = t & 63;
        const int rg = (t >> 6) & 1;
        const int hq = t >> 7;
        const int h0 = hq * 64;
        ull acc[2] = {0ULL, 0ULL};
        #pragma unroll 8
        for (int h = h0; h < h0 + 64; h++) {
            const float w = __ldg(&W1[h * DEMB + e]);
            const ull wp = pk2(w, w);
            const ull* oxp = (const ull*)&oxT[h][4 * rg];
            fma2(acc[0], oxp[0], wp);
            fma2(acc[1], oxp[1], wp);
        }
        if (hq > 0) {
            const float2 a0 = upk(acc[0]), a1 = upk(acc[1]);
            *(float4*)&red[((hq - 1) * 128 + rg * 64 + e) * 4] =
                make_float4(a0.x, a0.y, a1.x, a1.y);
        }
        __syncthreads();
        if (hq == 0) {
            const float2 a0 = upk(acc[0]), a1 = upk(acc[1]);
            float p[4] = {a0.x, a0.y, a1.x, a1.y};
            #pragma unroll
            for (int ss = 0; ss < 3; ss++) {
                const float4 rv = *(const float4*)&red[(ss * 128 + rg * 64 + e) * 4];
                p[0] += rv.x; p[1] += rv.y; p[2] += rv.z; p[3] += rv.w;
            }
            const float bb1 = b1[e];
            #pragma unroll
            for (int pp = 0; pp < 4; pp++) {
                const float v = fmaxf(p[pp] + bb1, 0.f);
                g_emb[(row0 + 4 * rg + pp) * DEMB + e] = v;
                embS[4 * rg + pp][e] = v;
            }
        }
    }
    __syncthreads();

    // ---- sq ----
    if (t < RA) {
        float s = 0.f;
        #pragma unroll
        for (int e = 0; e < DEMB; e++) {
            const float v = embS[t][e];
            s = fmaf(v, v, s);
        }
        g_sq[row0 + t] = s;
    }
}

// ============================================================
// Kernel B (round-8 structure + 1-MUFU tanh sigmoid):
// 64 i-rows x 256 j-cols strip of A per block. GEMM1 ->
// sigmoid+eye -> adj + GEMM2. grid (8, 32), 2 blocks/SM.
// ============================================================
__global__ void __launch_bounds__(256, 2) kB(
    const float* __restrict__ tempp,
    const float* __restrict__ thetap,
    float* __restrict__ adj_out)
{
    extern __shared__ float sm[];
    float* embIs = sm;                    // [64][68] k-major
    float* embJs = embIs + 64 * 68;       // [64][68] k-major
    float* xls   = embJs + 64 * 68;       // [64][132] j-major, padded
    float* As    = xls + 64 * 132;        // [64][68]
    float* sqJs  = As + 64 * 68;          // [64]
    float* degsh = sqJs + 64;             // [64][16]

    const int t  = threadIdx.x;
    const int s  = blockIdx.x;            // strip
    const int i0 = blockIdx.y * BI;
    const int jstart = s * STRIPJ;

    const float c1 = 1.0f + *tempp;
    const float c2 = 5.0f + *thetap;

    // stage embI transposed (k-major)
    #pragma unroll
    for (int idx = t; idx < BI * DEMB; idx += 256) {
        const int k = idx & 63, r = idx >> 6;
        embIs[k * 68 + r] = g_emb[(i0 + r) * DEMB + k];
    }

    // GEMM1 coords: 4 rows x 4 cols per thread
    const int r0 = (t >> 4) * 4;
    const int c0 = (t & 15) * 4;
    const float4 sqI = *(const float4*)&g_sq[i0 + r0];
    float degA[4] = {0.f, 0.f, 0.f, 0.f};

    // GEMM2 coords: rows {2q, 2q+1}, cols {g*4 + 32u + 0..3}
    const int q = t >> 3;
    const int g = t & 7;
    ull yac[2][8];
    #pragma unroll
    for (int r = 0; r < 2; r++)
        #pragma unroll
        for (int p = 0; p < 8; p++) yac[r][p] = 0ULL;

    for (int cj = 0; cj < STRIPJ / BJ; cj++) {
        const int jb = jstart + cj * BJ;
        __syncthreads();   // prev-iter readers done before overwrite

        // stage embJ transposed
        #pragma unroll
        for (int idx = t; idx < BJ * DEMB; idx += 256) {
            const int k = idx & 63, jl = idx >> 6;
            embJs[k * 68 + jl] = g_emb[(jb + jl) * DEMB + k];
        }
        if (t < BJ) sqJs[t] = g_sq[jb + t];
        // stage x_last chunk [64][132-padded] via float4
        {
            const float4* src = (const float4*)(g_xlast + (size_t)jb * DIN);
            #pragma unroll
            for (int idx = t; idx < BJ * DIN / 4; idx += 256) {
                const int row = idx >> 5, c4 = idx & 31;
                *(float4*)&xls[row * 132 + c4 * 4] = src[idx];
            }
        }
        __syncthreads();

        // ---- GEMM1: 4x4 per thread over k=64, packed j-pairs ----
        ull acc[4][2];
        #pragma unroll
        for (int r = 0; r < 4; r++) { acc[r][0] = 0ULL; acc[r][1] = 0ULL; }
        #pragma unroll 4
        for (int k = 0; k < DEMB; k++) {
            const float4 ai = *(const float4*)&embIs[k * 68 + r0];
            const float4 bj = *(const float4*)&embJs[k * 68 + c0];
            const ull b01 = pk2(bj.x, bj.y);
            const ull b23 = pk2(bj.z, bj.w);
            ull aa;
            aa = pk2(ai.x, ai.x); fma2(acc[0][0], aa, b01); fma2(acc[0][1], aa, b23);
            aa = pk2(ai.y, ai.y); fma2(acc[1][0], aa, b01); fma2(acc[1][1], aa, b23);
            aa = pk2(ai.z, ai.z); fma2(acc[2][0], aa, b01); fma2(acc[2][1], aa, b23);
            aa = pk2(ai.w, ai.w); fma2(acc[3][0], aa, b01); fma2(acc[3][1], aa, b23);
        }

        // ---- epilogue: sigmoid + eye, write adj, stash A tile, deg ----
        {
            const float4 sqJ = *(const float4*)&sqJs[c0];
            const int jbase = jb + c0;
            const float si[4] = {sqI.x, sqI.y, sqI.z, sqI.w};
            #pragma unroll
            for (int rr = 0; rr < 4; rr++) {
                const float2 g0 = upk(acc[rr][0]);
                const float2 g1 = upk(acc[rr][1]);
                const float zi = si[rr];
                const int i = i0 + r0 + rr;
                float4 w;
                w.x = sigmoidf(fmaf(c1, 2.f * g0.x - zi - sqJ.x, c2));
                w.y = sigmoidf(fmaf(c1, 2.f * g0.y - zi - sqJ.y, c2));
                w.z = sigmoidf(fmaf(c1, 2.f * g1.x - zi - sqJ.z, c2));
                w.w = sigmoidf(fmaf(c1, 2.f * g1.y - zi - sqJ.w, c2));
                if (i == jbase)     w.x += 1.f;
                if (i == jbase + 1) w.y += 1.f;
                if (i == jbase + 2) w.z += 1.f;
                if (i == jbase + 3) w.w += 1.f;
                degA[rr] += (w.x + w.y) + (w.z + w.w);
                *(float4*)(adj_out + (size_t)i * NN + jbase) = w;
                *(float4*)&As[(r0 + rr) * 68 + c0] = w;
            }
        }
        __syncthreads();

        // ---- GEMM2: y[64][128] += A[64][64] @ xls[64][128] ----
        #pragma unroll 4
        for (int c = 0; c < BJ; c++) {
            const float a0 = As[(2 * q) * 68 + c];
            const float a1 = As[(2 * q + 1) * 68 + c];
            const ull A0 = pk2(a0, a0);
            const ull A1 = pk2(a1, a1);
            #pragma unroll
            for (int u = 0; u < 4; u++) {
                const float4 xv = *(const float4*)&xls[c * 132 + g * 4 + 32 * u];
                const ull x01 = pk2(xv.x, xv.y);
                const ull x23 = pk2(xv.z, xv.w);
                fma2(yac[0][2 * u],     A0, x01);
                fma2(yac[0][2 * u + 1], A0, x23);
                fma2(yac[1][2 * u],     A1, x01);
                fma2(yac[1][2 * u + 1], A1, x23);
            }
        }
    }

    // write y partials
    #pragma unroll
    for (int r = 0; r < 2; r++) {
        float* base = g_ypart + ((size_t)s * NN + i0 + 2 * q + r) * DIN;
        #pragma unroll
        for (int u = 0; u < 4; u++) {
            const float2 p0 = upk(yac[r][2 * u]);
            const float2 p1 = upk(yac[r][2 * u + 1]);
            *(float4*)(base + g * 4 + 32 * u) = make_float4(p0.x, p0.y, p1.x, p1.y);
        }
    }

    // deg reduction (deterministic)
    #pragma unroll
    for (int rr = 0; rr < 4; rr++)
        degsh[(r0 + rr) * 16 + (t & 15)] = degA[rr];
    __syncthreads();
    if (t < BI) {
        float sdeg = 0.f;
        #pragma unroll
        for (int gg = 0; gg < 16; gg++) sdeg += degsh[t * 16 + gg];
        g_degpart[s * NN + i0 + t] = sdeg;
    }
}

// ============================================================
// Kernel C: out = relu( (sum_s y_part) / (sum_s deg_part) )
// float4 per thread; deg is warp-uniform -> broadcast LDG.
// ============================================================
__global__ void __launch_bounds__(256) kC(float* __restrict__ out)
{
    const int idx = blockIdx.x * 256 + threadIdx.x;  // < N*DIN/4
    const int i  = idx >> 5;
    const int d4 = (idx & 31) * 4;
    float deg = 0.f;
    #pragma unroll
    for (int s = 0; s < NSTRIP; s++) deg += g_degpart[s * NN + i];
    float4 y = make_float4(0.f, 0.f, 0.f, 0.f);
    #pragma unroll
    for (int s = 0; s < NSTRIP; s++) {
        const float4 p = *(const float4*)&g_ypart[((size_t)s * NN + i) * DIN + d4];
        y.x += p.x; y.y += p.y; y.z += p.z; y.w += p.w;
    }
    const float inv = 1.0f / deg;
    float4 o;
    o.x = fmaxf(y.x * inv, 0.f);
    o.y = fmaxf(y.y * inv, 0.f);
    o.z = fmaxf(y.z * inv, 0.f);
    o.w = fmaxf(y.w * inv, 0.f);
    *(float4*)(out + (size_t)i * DIN + d4) = o;
}

// ============================================================
extern "C" void kernel_launch(void* const* d_in, const int* in_sizes, int n_in,
                              void* d_out, int out_size)
{
    const float* x     = (const float*)d_in[0];
    // d_in[1] = adj : unused (only its shape matters in the reference)
    const float* W0    = (const float*)d_in[2];
    const float* b0    = (const float*)d_in[3];
    const float* W1    = (const float*)d_in[4];
    const float* b1    = (const float*)d_in[5];
    const float* W2    = (const float*)d_in[6];
    const float* b2    = (const float*)d_in[7];
    const float* temp  = (const float*)d_in[8];
    const float* theta = (const float*)d_in[9];

    float* out     = (float*)d_out;          // [N, DIN] first
    float* adj_out = out + NN * DIN;         // then [N*N] adjacency

    kA<<<NN / RA, 512>>>(x, W0, b0, W1, b1, W2, b2);

    const int smemB = (64 * 68 + 64 * 68 + 64 * 132 + 64 * 68 + 64 + 64 * 16) * 4;
    cudaFuncSetAttribute(kB, cudaFuncAttributeMaxDynamicSharedMemorySize, smemB);
    dim3 gB(NSTRIP, NN / BI);
    kB<<<gB, 256, smemB>>>(temp, theta, adj_out);

    kC<<<NN * DIN / 4 / 256, 256>>>(out);
}

// round 17
// speedup vs baseline: 1.0448x; 1.0448x over previous
#include <cuda_runtime.h>

#define NN    2048
#define DIN   128
#define HH    256
#define DEMB  64
#define NSTRIP 8
#define STRIPJ (NN / NSTRIP)   // 256
#define BI    64
#define BJ    64
#define RA    8                // rows per kA block
#define XPAD  10               // xsT/oxT row pad

// -------- device scratch (no allocations allowed) --------
__device__ __align__(16) float g_embT[DEMB * NN];           // 512 KB (k-major)
__device__ __align__(16) float g_sq[NN];                    // 8 KB
__device__ __align__(16) float g_xlast[NN * DIN];           // 1 MB
__device__ __align__(16) float g_ypart[NSTRIP * NN * DIN];  // 8 MB
__device__ __align__(16) float g_degpart[NSTRIP * NN];      // 64 KB

// -------- packed fp32x2 helpers (exact fp32, 2 FMA / instr) --------
typedef unsigned long long ull;
__device__ __forceinline__ ull pk2(float a, float b) {
    ull r; asm("mov.b64 %0, {%1, %2};" : "=l"(r) : "f"(a), "f"(b)); return r;
}
__device__ __forceinline__ void fma2(ull& d, ull a, ull b) {
    asm("fma.rn.f32x2 %0, %1, %2, %0;" : "+l"(d) : "l"(a), "l"(b));
}
__device__ __forceinline__ float2 upk(ull v) {
    float2 f; asm("mov.b64 {%0, %1}, %2;" : "=f"(f.x), "=f"(f.y) : "l"(v)); return f;
}
// sigmoid via single-MUFU tanh: sigmoid(z) = 0.5*tanh(z/2) + 0.5
__device__ __forceinline__ float sigmoidf(float z) {
    float th;
    const float h = 0.5f * z;
    asm("tanh.approx.f32 %0, %1;" : "=f"(th) : "f"(h));
    return fmaf(0.5f, th, 0.5f);
}

// ============================================================
// Kernel A (round-13 body, measured 21.0us): out_x, emb, sq,
// x_last. 256 blocks x 8 rows, 512 threads, 2 blocks/SM.
// emb written TRANSPOSED (k-major) for conflict-free kB staging.
// ============================================================
__global__ void __launch_bounds__(512) kA(
    const float* __restrict__ x,
    const float* __restrict__ W0, const float* __restrict__ b0,
    const float* __restrict__ W1, const float* __restrict__ b1,
    const float* __restrict__ W2, const float* __restrict__ b2)
{
    __shared__ float xsT[DIN][XPAD];   // x rows transposed (k-major)
    __shared__ float oxT[HH][XPAD];    // out_x transposed
    __shared__ float embS[RA][DEMB + 1];
    __shared__ float red[3 * 128 * 4]; // stage2 k-split partials

    const int t = threadIdx.x;
    const int row0 = blockIdx.x * RA;

    #pragma unroll
    for (int idx = t; idx < RA * DIN; idx += 512) {
        const int r = idx >> 7, k = idx & 127;
        xsT[k][r] = x[row0 * DIN + idx];
    }
    __syncthreads();

    // ---- merged stage 1 (out_x, col h, 4 rows) + stage 3 (x_last, col d, 2 rows) ----
    {
        const int h    = t & 255;
        const int half = t >> 8;          // rows 4*half..4*half+3
        const int d    = t & 127;
        const int q    = t >> 7;          // rows 2q, 2q+1
        ull acc1[2] = {0ULL, 0ULL};
        ull acc3 = 0ULL;

        #pragma unroll 2
        for (int kk = 0; kk < DIN; kk += 8) {
            float w0r[8], w2r[8];
            #pragma unroll
            for (int u = 0; u < 8; u++) {
                w0r[u] = W0[(kk + u) * HH + h];
                w2r[u] = W2[(kk + u) * DIN + d];
            }
            #pragma unroll
            for (int u = 0; u < 8; u++) {
                const float* xk = &xsT[kk + u][0];
                const ull w0p = pk2(w0r[u], w0r[u]);
                const ull* xr1 = (const ull*)(xk + 4 * half);
                fma2(acc1[0], xr1[0], w0p);
                fma2(acc1[1], xr1[1], w0p);
                const ull w2p = pk2(w2r[u], w2r[u]);
                fma2(acc3, *(const ull*)(xk + 2 * q), w2p);
            }
        }

        const float bb0 = b0[h];
        #pragma unroll
        for (int p = 0; p < 2; p++) {
            const float2 v = upk(acc1[p]);
            oxT[h][4 * half + 2 * p]     = fmaxf(v.x + bb0, 0.f);
            oxT[h][4 * half + 2 * p + 1] = fmaxf(v.y + bb0, 0.f);
        }
        const float bb2 = b2[d];
        const float2 v3 = upk(acc3);
        g_xlast[(row0 + 2 * q) * DIN + d]     = v3.x + bb2;
        g_xlast[(row0 + 2 * q + 1) * DIN + d] = v3.y + bb2;
    }
    __syncthreads();

    // ---- stage 2: emb [8, 64]; e = t&63, k-quarter split ----
    {
        const int e  = t & 63;
        const int rg = (t >> 6) & 1;
        const int hq = t >> 7;
        const int h0 = hq * 64;
        ull acc[2] = {0ULL, 0ULL};
        #pragma unroll 8
        for (int h = h0; h < h0 + 64; h++) {
            const float w = __ldg(&W1[h * DEMB + e]);
            const ull wp = pk2(w, w);
            const ull* oxp = (const ull*)&oxT[h][4 * rg];
            fma2(acc[0], oxp[0], wp);
            fma2(acc[1], oxp[1], wp);
        }
        if (hq > 0) {
            const float2 a0 = upk(acc[0]), a1 = upk(acc[1]);
            *(float4*)&red[((hq - 1) * 128 + rg * 64 + e) * 4] =
                make_float4(a0.x, a0.y, a1.x, a1.y);
        }
        __syncthreads();
        if (hq == 0) {
            const float2 a0 = upk(acc[0]), a1 = upk(acc[1]);
            float p[4] = {a0.x, a0.y, a1.x, a1.y};
            #pragma unroll
            for (int ss = 0; ss < 3; ss++) {
                const float4 rv = *(const float4*)&red[(ss * 128 + rg * 64 + e) * 4];
                p[0] += rv.x; p[1] += rv.y; p[2] += rv.z; p[3] += rv.w;
            }
            const float bb1 = b1[e];
            #pragma unroll
            for (int pp = 0; pp < 4; pp++) {
                const float v = fmaxf(p[pp] + bb1, 0.f);
                g_embT[e * NN + row0 + 4 * rg + pp] = v;   // transposed
                embS[4 * rg + pp][e] = v;
            }
        }
    }
    __syncthreads();

    // ---- sq ----
    if (t < RA) {
        float s = 0.f;
        #pragma unroll
        for (int e = 0; e < DEMB; e++) {
            const float v = embS[t][e];
            s = fmaf(v, v, s);
        }
        g_sq[row0 + t] = s;
    }
}

// ============================================================
// Kernel B (round-8 structure + tanh sigmoid + conflict-free
// float4 staging from g_embT): 64 i-rows x 256 j-cols strip.
// grid (8, 32), 2 blocks/SM.
// ============================================================
__global__ void __launch_bounds__(256, 2) kB(
    const float* __restrict__ tempp,
    const float* __restrict__ thetap,
    float* __restrict__ adj_out)
{
    extern __shared__ float sm[];
    float* embIs = sm;                    // [64][68] k-major
    float* embJs = embIs + 64 * 68;       // [64][68] k-major
    float* xls   = embJs + 64 * 68;       // [64][132] j-major, padded
    float* As    = xls + 64 * 132;        // [64][68]
    float* sqJs  = As + 64 * 68;          // [64]
    float* degsh = sqJs + 64;             // [64][16]

    const int t  = threadIdx.x;
    const int s  = blockIdx.x;            // strip
    const int i0 = blockIdx.y * BI;
    const int jstart = s * STRIPJ;

    const float c1 = 1.0f + *tempp;
    const float c2 = 5.0f + *thetap;

    // stage embI (k-major, float4, conflict-free)
    #pragma unroll
    for (int idx = t; idx < 64 * 16; idx += 256) {
        const int r4 = (idx & 15) * 4, k = idx >> 4;
        *(float4*)&embIs[k * 68 + r4] = *(const float4*)&g_embT[k * NN + i0 + r4];
    }

    // GEMM1 coords: 4 rows x 4 cols per thread
    const int r0 = (t >> 4) * 4;
    const int c0 = (t & 15) * 4;
    const float4 sqI = *(const float4*)&g_sq[i0 + r0];
    float degA[4] = {0.f, 0.f, 0.f, 0.f};

    // GEMM2 coords: rows {2q, 2q+1}, cols {g*4 + 32u + 0..3}
    const int q = t >> 3;
    const int g = t & 7;
    ull yac[2][8];
    #pragma unroll
    for (int r = 0; r < 2; r++)
        #pragma unroll
        for (int p = 0; p < 8; p++) yac[r][p] = 0ULL;

    for (int cj = 0; cj < STRIPJ / BJ; cj++) {
        const int jb = jstart + cj * BJ;
        __syncthreads();   // prev-iter readers done before overwrite

        // stage embJ (k-major, float4, conflict-free)
        #pragma unroll
        for (int idx = t; idx < 64 * 16; idx += 256) {
            const int j4 = (idx & 15) * 4, k = idx >> 4;
            *(float4*)&embJs[k * 68 + j4] =
                *(const float4*)&g_embT[k * NN + jb + j4];
        }
        if (t < BJ) sqJs[t] = g_sq[jb + t];
        // stage x_last chunk [64][132-padded] via float4
        {
            const float4* src = (const float4*)(g_xlast + (size_t)jb * DIN);
            #pragma unroll
            for (int idx = t; idx < BJ * DIN / 4; idx += 256) {
                const int row = idx >> 5, c4 = idx & 31;
                *(float4*)&xls[row * 132 + c4 * 4] = src[idx];
            }
        }
        __syncthreads();

        // ---- GEMM1: 4x4 per thread over k=64, packed j-pairs ----
        ull acc[4][2];
        #pragma unroll
        for (int r = 0; r < 4; r++) { acc[r][0] = 0ULL; acc[r][1] = 0ULL; }
        #pragma unroll 4
        for (int k = 0; k < DEMB; k++) {
            const float4 ai = *(const float4*)&embIs[k * 68 + r0];
            const float4 bj = *(const float4*)&embJs[k * 68 + c0];
            const ull b01 = pk2(bj.x, bj.y);
            const ull b23 = pk2(bj.z, bj.w);
            ull aa;
            aa = pk2(ai.x, ai.x); fma2(acc[0][0], aa, b01); fma2(acc[0][1], aa, b23);
            aa = pk2(ai.y, ai.y); fma2(acc[1][0], aa, b01); fma2(acc[1][1], aa, b23);
            aa = pk2(ai.z, ai.z); fma2(acc[2][0], aa, b01); fma2(acc[2][1], aa, b23);
            aa = pk2(ai.w, ai.w); fma2(acc[3][0], aa, b01); fma2(acc[3][1], aa, b23);
        }

        // ---- epilogue: sigmoid + eye, write adj, stash A tile, deg ----
        {
            const float4 sqJ = *(const float4*)&sqJs[c0];
            const int jbase = jb + c0;
            const float si[4] = {sqI.x, sqI.y, sqI.z, sqI.w};
            #pragma unroll
            for (int rr = 0; rr < 4; rr++) {
                const float2 g0 = upk(acc[rr][0]);
                const float2 g1 = upk(acc[rr][1]);
                const float zi = si[rr];
                const int i = i0 + r0 + rr;
                float4 w;
                w.x = sigmoidf(fmaf(c1, 2.f * g0.x - zi - sqJ.x, c2));
                w.y = sigmoidf(fmaf(c1, 2.f * g0.y - zi - sqJ.y, c2));
                w.z = sigmoidf(fmaf(c1, 2.f * g1.x - zi - sqJ.z, c2));
                w.w = sigmoidf(fmaf(c1, 2.f * g1.y - zi - sqJ.w, c2));
                if (i == jbase)     w.x += 1.f;
                if (i == jbase + 1) w.y += 1.f;
                if (i == jbase + 2) w.z += 1.f;
                if (i == jbase + 3) w.w += 1.f;
                degA[rr] += (w.x + w.y) + (w.z + w.w);
                *(float4*)(adj_out + (size_t)i * NN + jbase) = w;
                *(float4*)&As[(r0 + rr) * 68 + c0] = w;
            }
        }
        __syncthreads();

        // ---- GEMM2: y[64][128] += A[64][64] @ xls[64][128] ----
        #pragma unroll 4
        for (int c = 0; c < BJ; c++) {
            const float a0 = As[(2 * q) * 68 + c];
            const float a1 = As[(2 * q + 1) * 68 + c];
            const ull A0 = pk2(a0, a0);
            const ull A1 = pk2(a1, a1);
            #pragma unroll
            for (int u = 0; u < 4; u++) {
                const float4 xv = *(const float4*)&xls[c * 132 + g * 4 + 32 * u];
                const ull x01 = pk2(xv.x, xv.y);
                const ull x23 = pk2(xv.z, xv.w);
                fma2(yac[0][2 * u],     A0, x01);
                fma2(yac[0][2 * u + 1], A0, x23);
                fma2(yac[1][2 * u],     A1, x01);
                fma2(yac[1][2 * u + 1], A1, x23);
            }
        }
    }

    // write y partials
    #pragma unroll
    for (int r = 0; r < 2; r++) {
        float* base = g_ypart + ((size_t)s * NN + i0 + 2 * q + r) * DIN;
        #pragma unroll
        for (int u = 0; u < 4; u++) {
            const float2 p0 = upk(yac[r][2 * u]);
            const float2 p1 = upk(yac[r][2 * u + 1]);
            *(float4*)(base + g * 4 + 32 * u) = make_float4(p0.x, p0.y, p1.x, p1.y);
        }
    }

    // deg reduction (deterministic)
    #pragma unroll
    for (int rr = 0; rr < 4; rr++)
        degsh[(r0 + rr) * 16 + (t & 15)] = degA[rr];
    __syncthreads();
    if (t < BI) {
        float sdeg = 0.f;
        #pragma unroll
        for (int gg = 0; gg < 16; gg++) sdeg += degsh[t * 16 + gg];
        g_degpart[s * NN + i0 + t] = sdeg;
    }
}

// ============================================================
// Kernel C: out = relu( (sum_s y_part) / (sum_s deg_part) )
// float4 per thread; deg is warp-uniform -> broadcast LDG.
// ============================================================
__global__ void __launch_bounds__(256) kC(float* __restrict__ out)
{
    const int idx = blockIdx.x * 256 + threadIdx.x;  // < N*DIN/4
    const int i  = idx >> 5;
    const int d4 = (idx & 31) * 4;
    float deg = 0.f;
    #pragma unroll
    for (int s = 0; s < NSTRIP; s++) deg += g_degpart[s * NN + i];
    float4 y = make_float4(0.f, 0.f, 0.f, 0.f);
    #pragma unroll
    for (int s = 0; s < NSTRIP; s++) {
        const float4 p = *(const float4*)&g_ypart[((size_t)s * NN + i) * DIN + d4];
        y.x += p.x; y.y += p.y; y.z += p.z; y.w += p.w;
    }
    const float inv = 1.0f / deg;
    float4 o;
    o.x = fmaxf(y.x * inv, 0.f);
    o.y = fmaxf(y.y * inv, 0.f);
    o.z = fmaxf(y.z * inv, 0.f);
    o.w = fmaxf(y.w * inv, 0.f);
    *(float4*)(out + (size_t)i * DIN + d4) = o;
}

// ============================================================
extern "C" void kernel_launch(void* const* d_in, const int* in_sizes, int n_in,
                              void* d_out, int out_size)
{
    const float* x     = (const float*)d_in[0];
    // d_in[1] = adj : unused (only its shape matters in the reference)
    const float* W0    = (const float*)d_in[2];
    const float* b0    = (const float*)d_in[3];
    const float* W1    = (const float*)d_in[4];
    const float* b1    = (const float*)d_in[5];
    const float* W2    = (const float*)d_in[6];
    const float* b2    = (const float*)d_in[7];
    const float* temp  = (const float*)d_in[8];
    const float* theta = (const float*)d_in[9];

    float* out     = (float*)d_out;          // [N, DIN] first
    float* adj_out = out + NN * DIN;         // then [N*N] adjacency

    kA<<<NN / RA, 512>>>(x, W0, b0, W1, b1, W2, b2);

    const int smemB = (64 * 68 + 64 * 68 + 64 * 132 + 64 * 68 + 64 + 64 * 16) * 4;
    cudaFuncSetAttribute(kB, cudaFuncAttributeMaxDynamicSharedMemorySize, smemB);
    dim3 gB(NSTRIP, NN / BI);
    kB<<<gB, 256, smemB>>>(temp, theta, adj_out);

    kC<<<NN * DIN / 4 / 256, 256>>>(out);
}